// round 15
// baseline (speedup 1.0000x reference)
#include <cuda_runtime.h>
#include <cuda_bf16.h>
#include <cuda_fp16.h>
#include <mma.h>
#include <cuda_pipeline.h>
#include <cstdint>

using namespace nvcuda;

// ---------------------------------------------------------------------------
// JKNet R15: output projection swapped with segsum:
//   out = segsum([h1 h2 h3]) @ Wout  ==  segsum(P) + bout, P = sum_l h_l@Wout_l
// P accumulated inside each conv GEMM's epilogue (second in-block GEMM vs
// Wout_l). Removes F images, dual-mode gathers, h2 write, and the separate
// K=384 final GEMM. Aggs are single-output; final pass is one plain P gather
// writing `out` directly.
// ---------------------------------------------------------------------------

#define NN 50000
#define EE 800000
#define DD 128
#define NPAD (NN + 64)

// ---------------- scratch ---------------------------------------------------
__device__ __half g_hf[NN * DD];        // fp16 feats
__device__ __half g_h0[NN * DD];
__device__ __half g_h1[NN * DD];
__device__ float  g_P [NPAD * DD];      // running h_l @ Wout_l accumulator
__device__ __nv_bfloat16 g_Ahi[NPAD * DD];
__device__ __nv_bfloat16 g_Alo[NPAD * DD];
__device__ float g_srcn[NN];
__device__ float g_dstn[NN];
__device__ int   g_outdeg[NN];
__device__ int   g_indeg [NN];
__device__ int   g_rowptr[NN + 1];
__device__ int   g_cursor[NN];
__device__ int2  g_edge[EE];            // (src, srcn bits)
__device__ int   g_bsum[256];
__device__ __nv_bfloat16 g_Bhi[6 * DD * DD];
__device__ __nv_bfloat16 g_Blo[6 * DD * DD];

// ---------------- CSR build -------------------------------------------------
__global__ void zero_ints(int* __restrict__ a, int* __restrict__ b, int n) {
    int i = blockIdx.x * blockDim.x + threadIdx.x;
    if (i < n) { a[i] = 0; b[i] = 0; }
}
__global__ void deg_hist(const int* __restrict__ src, const int* __restrict__ dst,
                         int* __restrict__ outdeg, int* __restrict__ indeg, int e) {
    int i = blockIdx.x * blockDim.x + threadIdx.x;
    if (i < e) { atomicAdd(&outdeg[src[i]], 1); atomicAdd(&indeg[dst[i]], 1); }
}
__global__ void scan_block_sums(const int* __restrict__ deg, int* __restrict__ bsum, int n) {
    __shared__ int s[256];
    int i = blockIdx.x * 256 + threadIdx.x;
    s[threadIdx.x] = (i < n) ? deg[i] : 0;
    __syncthreads();
    for (int off = 128; off > 0; off >>= 1) {
        if (threadIdx.x < off) s[threadIdx.x] += s[threadIdx.x + off];
        __syncthreads();
    }
    if (threadIdx.x == 0) bsum[blockIdx.x] = s[0];
}
__global__ void scan_bsums(int* __restrict__ bsum, int nb) {
    __shared__ int s[256];
    int t = threadIdx.x;
    int v = (t < nb) ? bsum[t] : 0;
    s[t] = v;
    __syncthreads();
    for (int off = 1; off < 256; off <<= 1) {
        int add = (t >= off) ? s[t - off] : 0;
        __syncthreads();
        s[t] += add;
        __syncthreads();
    }
    if (t < nb) bsum[t] = s[t] - v;
}
__global__ void scan_final(const int* __restrict__ deg, const int* __restrict__ bsum,
                           const int* __restrict__ outdeg,
                           int* __restrict__ rowptr, int* __restrict__ cursor,
                           float* __restrict__ sn, float* __restrict__ dn,
                           int n, int etot) {
    __shared__ int s[256];
    int t = threadIdx.x;
    int i = blockIdx.x * 256 + t;
    int v = (i < n) ? deg[i] : 0;
    s[t] = v;
    __syncthreads();
    for (int off = 1; off < 256; off <<= 1) {
        int add = (t >= off) ? s[t - off] : 0;
        __syncthreads();
        s[t] += add;
        __syncthreads();
    }
    int ex = bsum[blockIdx.x] + s[t] - v;
    if (i < n) {
        rowptr[i] = ex;
        cursor[i] = ex;
        sn[i] = rsqrtf((float)max(outdeg[i], 1));
        dn[i] = rsqrtf((float)max(v, 1));
    }
    if (i == 0) rowptr[n] = etot;
}
__global__ void scatter_edges(const int* __restrict__ src, const int* __restrict__ dst,
                              const float* __restrict__ srcn,
                              int* __restrict__ cursor, int2* __restrict__ edge, int e) {
    int i = blockIdx.x * blockDim.x + threadIdx.x;
    if (i < e) {
        int s = src[i];
        int p = atomicAdd(&cursor[dst[i]], 1);
        edge[p] = make_int2(s, __float_as_int(srcn[s]));
    }
}

// ---------------- input conversion: feats -> fp16, W -> bf16 hi/lo ----------
__global__ void conv_inputs(const float* __restrict__ feats,
                            const float* __restrict__ W0, const float* __restrict__ W1,
                            const float* __restrict__ W2, const float* __restrict__ Wout,
                            __half* __restrict__ hf,
                            __nv_bfloat16* __restrict__ hi, __nv_bfloat16* __restrict__ lo,
                            int nfeat4) {
    int idx = blockIdx.x * blockDim.x + threadIdx.x;
    if (idx < nfeat4) {
        float4 v = ((const float4*)feats)[idx];
        __half2 p0 = __floats2half2_rn(v.x, v.y);
        __half2 p1 = __floats2half2_rn(v.z, v.w);
        *(uint2*)(hf + (size_t)idx * 4) = make_uint2(*(uint32_t*)&p0, *(uint32_t*)&p1);
    }
    if (idx < 6 * DD * DD) {
        int m = idx / (DD * DD);
        int rem = idx % (DD * DD);
        const float* src = (m == 0) ? W0 : (m == 1) ? W1 : (m == 2) ? W2
                                         : (Wout + (m - 3) * DD * DD);
        float v = src[rem];
        __nv_bfloat16 h = __float2bfloat16(v);
        __nv_bfloat16 l = __float2bfloat16(v - __bfloat162float(h));
        hi[idx] = h;
        lo[idx] = l;
    }
}

// split 8 floats (cols sl*8..+7 of row r) into bf16 hi/lo images, 16B stores
__device__ __forceinline__ void split_store8(__nv_bfloat16* __restrict__ hi,
                                             __nv_bfloat16* __restrict__ lo,
                                             int r, int sl, const float* v) {
    uint4 ph, pl;
    uint32_t* phh = (uint32_t*)&ph;
    uint32_t* pll = (uint32_t*)&pl;
#pragma unroll
    for (int j = 0; j < 4; j++) {
        __nv_bfloat162 h2, l2;
        h2.x = __float2bfloat16(v[2 * j]);
        h2.y = __float2bfloat16(v[2 * j + 1]);
        l2.x = __float2bfloat16(v[2 * j]     - __bfloat162float(h2.x));
        l2.y = __float2bfloat16(v[2 * j + 1] - __bfloat162float(h2.y));
        phh[j] = *(uint32_t*)&h2;
        pll[j] = *(uint32_t*)&l2;
    }
    *(uint4*)(hi + (size_t)r * 128 + sl * 8) = ph;
    *(uint4*)(lo + (size_t)r * 128 + sl * 8) = pl;
}

// convert uint4 of 8 halves to 8 floats
__device__ __forceinline__ void cvt8(uint4 u, float* f) {
    __half2* h = (__half2*)&u;
#pragma unroll
    for (int j = 0; j < 4; j++) {
        float2 p = __half22float2(h[j]);
        f[2 * j] = p.x;
        f[2 * j + 1] = p.y;
    }
}

// ---------------- fp16 scaled aggregation (half-warp per node) --------------
__global__ void agg_h(const __half* __restrict__ X,
                      const int* __restrict__ rowptr,
                      const int2* __restrict__ edge,
                      const float* __restrict__ dstn,
                      __nv_bfloat16* __restrict__ Ahi, __nv_bfloat16* __restrict__ Alo,
                      int n) {
    int node = (blockIdx.x * blockDim.x + threadIdx.x) >> 4;
    int sl   = threadIdx.x & 15;
    if (node >= n) return;
    int beg = rowptr[node];
    int end = rowptr[node + 1];

    float aS[8];
#pragma unroll
    for (int j = 0; j < 8; j++) aS[j] = 0.f;

    int e = beg;
    for (; e + 7 < end; e += 8) {
        int2 ed[8];
#pragma unroll
        for (int t = 0; t < 8; t++) ed[t] = edge[e + t];
        uint4 u[8];
#pragma unroll
        for (int t = 0; t < 8; t++)
            u[t] = *(const uint4*)(X + (size_t)ed[t].x * 128 + sl * 8);
#pragma unroll
        for (int t = 0; t < 8; t++) {
            float f[8];
            cvt8(u[t], f);
            float nv = __int_as_float(ed[t].y);
#pragma unroll
            for (int j = 0; j < 8; j++) aS[j] += f[j] * nv;
        }
    }
    for (; e + 3 < end; e += 4) {
        int2 ed[4];
#pragma unroll
        for (int t = 0; t < 4; t++) ed[t] = edge[e + t];
        uint4 u[4];
#pragma unroll
        for (int t = 0; t < 4; t++)
            u[t] = *(const uint4*)(X + (size_t)ed[t].x * 128 + sl * 8);
#pragma unroll
        for (int t = 0; t < 4; t++) {
            float f[8];
            cvt8(u[t], f);
            float nv = __int_as_float(ed[t].y);
#pragma unroll
            for (int j = 0; j < 8; j++) aS[j] += f[j] * nv;
        }
    }
    for (; e < end; e++) {
        int2 e0 = edge[e];
        uint4 u0 = *(const uint4*)(X + (size_t)e0.x * 128 + sl * 8);
        float f0[8];
        cvt8(u0, f0);
        float n0 = __int_as_float(e0.y);
#pragma unroll
        for (int j = 0; j < 8; j++) aS[j] += f0[j] * n0;
    }
    float dn = dstn[node];
#pragma unroll
    for (int j = 0; j < 8; j++) aS[j] *= dn;
    split_store8(Ahi, Alo, node, sl, aS);
}

// ---------------- final gather: out = segsum(P) + bout ----------------------
__global__ void pgather(const float* __restrict__ P,
                        const int* __restrict__ rowptr,
                        const int2* __restrict__ edge,
                        const float* __restrict__ bout,
                        float* __restrict__ out, int n) {
    int node = (blockIdx.x * blockDim.x + threadIdx.x) >> 5;
    int lane = threadIdx.x & 31;
    if (node >= n) return;
    int beg = rowptr[node];
    int end = rowptr[node + 1];
    const float4* P4 = (const float4*)P;

    float4 a = make_float4(0.f, 0.f, 0.f, 0.f);
    int e = beg;
    for (; e + 3 < end; e += 4) {
        int s0 = edge[e].x, s1 = edge[e + 1].x;
        int s2 = edge[e + 2].x, s3 = edge[e + 3].x;
        float4 v0 = P4[s0 * 32 + lane];
        float4 v1 = P4[s1 * 32 + lane];
        float4 v2 = P4[s2 * 32 + lane];
        float4 v3 = P4[s3 * 32 + lane];
        a.x += v0.x + v1.x + v2.x + v3.x;
        a.y += v0.y + v1.y + v2.y + v3.y;
        a.z += v0.z + v1.z + v2.z + v3.z;
        a.w += v0.w + v1.w + v2.w + v3.w;
    }
    for (; e < end; e++) {
        float4 v0 = P4[edge[e].x * 32 + lane];
        a.x += v0.x; a.y += v0.y; a.z += v0.z; a.w += v0.w;
    }
    float4 b = ((const float4*)bout)[lane];
    a.x += b.x; a.y += b.y; a.z += b.z; a.w += b.w;
    ((float4*)out)[node * 32 + lane] = a;
}

// ---------------- conv GEMM with fused P projection --------------------------
#define ALD 136
#define BLD 136
#define SM_AHI 0
#define SM_ALO 17408
#define SM_BHI 34816
#define SM_BLO 69632
#define SM_BIAS 104448
#define SM_TOT 112640

// LAYER 0: P = h@Wo, write Hout. LAYER 1: P += , write Hout. LAYER 2: P +=, no Hout.
template <int LAYER>
__global__ void __launch_bounds__(256, 2)
conv_gemm(const __nv_bfloat16* __restrict__ Ah, const __nv_bfloat16* __restrict__ Al,
          const __nv_bfloat16* __restrict__ Bh, const __nv_bfloat16* __restrict__ Bl,
          const __nv_bfloat16* __restrict__ Woh, const __nv_bfloat16* __restrict__ Wol,
          const float* __restrict__ bias,
          __half* __restrict__ Hout, float* __restrict__ P, int n) {
    extern __shared__ unsigned char smem[];
    __nv_bfloat16* sAhi = (__nv_bfloat16*)(smem + SM_AHI);
    __nv_bfloat16* sAlo = (__nv_bfloat16*)(smem + SM_ALO);
    __nv_bfloat16* sBhi = (__nv_bfloat16*)(smem + SM_BHI);
    __nv_bfloat16* sBlo = (__nv_bfloat16*)(smem + SM_BLO);
    float*         sBias = (float*)(smem + SM_BIAS);
    float*         smemF = (float*)(smem + SM_AHI);   // 32KB fp32 result tile

    const int tid  = threadIdx.x;
    const int wid  = tid >> 5;
    const int row0 = blockIdx.x * 64;
    const int rt = wid >> 1;
    const int ch = wid & 1;

    // ---- phase A staging: A images + W_l images ----
#pragma unroll
    for (int i = 0; i < 4; i++) {
        int idx = i * 256 + tid;
        int r   = idx >> 4;
        int c16 = idx & 15;
        size_t g = (size_t)(row0 + r) * 128 + c16 * 8;
        __pipeline_memcpy_async(sAhi + r * ALD + c16 * 8, Ah + g, 16);
        __pipeline_memcpy_async(sAlo + r * ALD + c16 * 8, Al + g, 16);
    }
#pragma unroll
    for (int i = 0; i < 8; i++) {
        int idx = i * 256 + tid;
        int r   = idx >> 4;
        int c16 = idx & 15;
        __pipeline_memcpy_async(sBhi + r * BLD + c16 * 8, Bh + r * 128 + c16 * 8, 16);
        __pipeline_memcpy_async(sBlo + r * BLD + c16 * 8, Bl + r * 128 + c16 * 8, 16);
    }
    __pipeline_commit();
    for (int idx = tid; idx < 2048; idx += 256)
        sBias[idx] = bias[(idx >> 8) * 16 + (idx & 15)];
    __pipeline_wait_prior(0);
    __syncthreads();

    // ---- phase A compute: acc = relu(A@W + bias) ----
    wmma::fragment<wmma::accumulator, 16, 16, 16, float> acc[4];
#pragma unroll
    for (int j = 0; j < 4; j++)
        wmma::load_matrix_sync(acc[j], sBias + (ch * 4 + j) * 256, 16, wmma::mem_row_major);
#pragma unroll
    for (int kk = 0; kk < 8; kk++) {
        wmma::fragment<wmma::matrix_a, 16, 16, 16, __nv_bfloat16, wmma::row_major> ah, al;
        wmma::load_matrix_sync(ah, sAhi + (rt * 16) * ALD + kk * 16, ALD);
        wmma::load_matrix_sync(al, sAlo + (rt * 16) * ALD + kk * 16, ALD);
#pragma unroll
        for (int j = 0; j < 4; j++) {
            int nt = ch * 4 + j;
            wmma::fragment<wmma::matrix_b, 16, 16, 16, __nv_bfloat16, wmma::row_major> bh, bl;
            wmma::load_matrix_sync(bh, sBhi + (kk * 16) * BLD + nt * 16, BLD);
            wmma::load_matrix_sync(bl, sBlo + (kk * 16) * BLD + nt * 16, BLD);
            wmma::mma_sync(acc[j], ah, bh, acc[j]);
            wmma::mma_sync(acc[j], ah, bl, acc[j]);
            wmma::mma_sync(acc[j], al, bh, acc[j]);
        }
    }
    __syncthreads();   // done reading sA/sB; free for phase B

    // ---- phase B staging kick: Wout_l into sB ----
#pragma unroll
    for (int i = 0; i < 8; i++) {
        int idx = i * 256 + tid;
        int r   = idx >> 4;
        int c16 = idx & 15;
        __pipeline_memcpy_async(sBhi + r * BLD + c16 * 8, Woh + r * 128 + c16 * 8, 16);
        __pipeline_memcpy_async(sBlo + r * BLD + c16 * 8, Wol + r * 128 + c16 * 8, 16);
    }
    __pipeline_commit();

    // ---- h tile: relu fragments -> smemF (fp32) ----
    if (row0 + rt * 16 + 16 <= n) {
#pragma unroll
        for (int j = 0; j < 4; j++) {
#pragma unroll
            for (int i = 0; i < acc[j].num_elements; i++)
                acc[j].x[i] = fmaxf(acc[j].x[i], 0.f);
            wmma::store_matrix_sync(smemF + (rt * 16) * 128 + (ch * 4 + j) * 16,
                                    acc[j], 128, wmma::mem_row_major);
        }
    }
    __syncthreads();

    // ---- read smemF to regs; write Hout fp16; then rewrite smem as A2 images ---
    float4 hreg[8];
#pragma unroll
    for (int i = 0; i < 8; i++) {
        int idx4 = i * 256 + tid;
        hreg[i] = ((const float4*)smemF)[idx4];
        if (LAYER < 2) {
            int r  = idx4 >> 5;
            int c4 = idx4 & 31;
            if (row0 + r < n) {
                __half2 p0 = __floats2half2_rn(hreg[i].x, hreg[i].y);
                __half2 p1 = __floats2half2_rn(hreg[i].z, hreg[i].w);
                *(uint2*)(Hout + (size_t)(row0 + r) * 128 + c4 * 4) =
                    make_uint2(*(uint32_t*)&p0, *(uint32_t*)&p1);
            }
        }
    }
    __syncthreads();   // all smemF reads done before overwrite
#pragma unroll
    for (int i = 0; i < 8; i++) {
        int idx4 = i * 256 + tid;
        int r  = idx4 >> 5;
        int c4 = idx4 & 31;
        __nv_bfloat162 h01, h23, l01, l23;
        h01.x = __float2bfloat16(hreg[i].x); h01.y = __float2bfloat16(hreg[i].y);
        h23.x = __float2bfloat16(hreg[i].z); h23.y = __float2bfloat16(hreg[i].w);
        l01.x = __float2bfloat16(hreg[i].x - __bfloat162float(h01.x));
        l01.y = __float2bfloat16(hreg[i].y - __bfloat162float(h01.y));
        l23.x = __float2bfloat16(hreg[i].z - __bfloat162float(h23.x));
        l23.y = __float2bfloat16(hreg[i].w - __bfloat162float(h23.y));
        *(uint2*)((unsigned char*)sAhi + (size_t)r * (ALD * 2) + c4 * 8) =
            make_uint2(*(uint32_t*)&h01, *(uint32_t*)&h23);
        *(uint2*)((unsigned char*)sAlo + (size_t)r * (ALD * 2) + c4 * 8) =
            make_uint2(*(uint32_t*)&l01, *(uint32_t*)&l23);
    }
    __pipeline_wait_prior(0);
    __syncthreads();

    // ---- phase B compute: P tile (+)= h @ Wout_l ----
    wmma::fragment<wmma::accumulator, 16, 16, 16, float> acc2[4];
    if (LAYER == 0) {
#pragma unroll
        for (int j = 0; j < 4; j++) wmma::fill_fragment(acc2[j], 0.f);
    } else {
#pragma unroll
        for (int j = 0; j < 4; j++)
            wmma::load_matrix_sync(acc2[j],
                P + (size_t)(row0 + rt * 16) * 128 + (ch * 4 + j) * 16,
                128, wmma::mem_row_major);
    }
#pragma unroll
    for (int kk = 0; kk < 8; kk++) {
        wmma::fragment<wmma::matrix_a, 16, 16, 16, __nv_bfloat16, wmma::row_major> ah, al;
        wmma::load_matrix_sync(ah, sAhi + (rt * 16) * ALD + kk * 16, ALD);
        wmma::load_matrix_sync(al, sAlo + (rt * 16) * ALD + kk * 16, ALD);
#pragma unroll
        for (int j = 0; j < 4; j++) {
            int nt = ch * 4 + j;
            wmma::fragment<wmma::matrix_b, 16, 16, 16, __nv_bfloat16, wmma::row_major> bh, bl;
            wmma::load_matrix_sync(bh, sBhi + (kk * 16) * BLD + nt * 16, BLD);
            wmma::load_matrix_sync(bl, sBlo + (kk * 16) * BLD + nt * 16, BLD);
            wmma::mma_sync(acc2[j], ah, bh, acc2[j]);
            wmma::mma_sync(acc2[j], ah, bl, acc2[j]);
            wmma::mma_sync(acc2[j], al, bh, acc2[j]);
        }
    }
    if (row0 + rt * 16 + 16 <= n) {
#pragma unroll
        for (int j = 0; j < 4; j++)
            wmma::store_matrix_sync(P + (size_t)(row0 + rt * 16) * 128 + (ch * 4 + j) * 16,
                                    acc2[j], 128, wmma::mem_row_major);
    }
}

// ---------------------------------------------------------------------------
extern "C" void kernel_launch(void* const* d_in, const int* in_sizes, int n_in,
                              void* d_out, int out_size) {
    const float* feats = (const float*)d_in[0];
    const int*   src   = (const int*)  d_in[1];
    const int*   dst   = (const int*)  d_in[2];
    const float* W0    = (const float*)d_in[3];
    const float* b0    = (const float*)d_in[4];
    const float* W1    = (const float*)d_in[5];
    const float* b1    = (const float*)d_in[6];
    const float* W2    = (const float*)d_in[7];
    const float* b2    = (const float*)d_in[8];
    const float* Wout  = (const float*)d_in[9];
    const float* bout  = (const float*)d_in[10];
    float*       out   = (float*)d_out;

    const int n = in_sizes[0] / DD;
    const int e = in_sizes[1];

    __half *hf, *h0, *h1;
    float *P, *srcn, *dstn;
    int *outdeg, *indeg, *rowptr, *cursor, *bsum;
    int2 *edge;
    __nv_bfloat16 *Ahi, *Alo, *Bhi, *Blo;
    cudaGetSymbolAddress((void**)&hf,     g_hf);
    cudaGetSymbolAddress((void**)&h0,     g_h0);
    cudaGetSymbolAddress((void**)&h1,     g_h1);
    cudaGetSymbolAddress((void**)&P,      g_P);
    cudaGetSymbolAddress((void**)&Ahi,    g_Ahi);
    cudaGetSymbolAddress((void**)&Alo,    g_Alo);
    cudaGetSymbolAddress((void**)&srcn,   g_srcn);
    cudaGetSymbolAddress((void**)&dstn,   g_dstn);
    cudaGetSymbolAddress((void**)&outdeg, g_outdeg);
    cudaGetSymbolAddress((void**)&indeg,  g_indeg);
    cudaGetSymbolAddress((void**)&rowptr, g_rowptr);
    cudaGetSymbolAddress((void**)&cursor, g_cursor);
    cudaGetSymbolAddress((void**)&edge,   g_edge);
    cudaGetSymbolAddress((void**)&bsum,   g_bsum);
    cudaGetSymbolAddress((void**)&Bhi,    g_Bhi);
    cudaGetSymbolAddress((void**)&Blo,    g_Blo);

    const int nbN   = (n + 255) / 256;
    const int nbE   = (e + 255) / 256;
    const int nbAgH = (n + 15) / 16;     // half-warp per node
    const int nbAgW = (n + 7) / 8;       // warp per node (pgather)
    const int nbT   = (n + 63) / 64;
    const int nfeat4 = n * DD / 4;
    const int nbCv  = (nfeat4 + 255) / 256;

    cudaFuncSetAttribute(conv_gemm<0>, cudaFuncAttributeMaxDynamicSharedMemorySize, SM_TOT);
    cudaFuncSetAttribute(conv_gemm<1>, cudaFuncAttributeMaxDynamicSharedMemorySize, SM_TOT);
    cudaFuncSetAttribute(conv_gemm<2>, cudaFuncAttributeMaxDynamicSharedMemorySize, SM_TOT);

    // ---- CSR build + norms + input conversion ----
    zero_ints      <<<nbN, 256>>>(outdeg, indeg, n);
    conv_inputs    <<<nbCv, 256>>>(feats, W0, W1, W2, Wout, hf, Bhi, Blo, nfeat4);
    deg_hist       <<<nbE, 256>>>(src, dst, outdeg, indeg, e);
    scan_block_sums<<<nbN, 256>>>(indeg, bsum, n);
    scan_bsums     <<<1,   256>>>(bsum, nbN);
    scan_final     <<<nbN, 256>>>(indeg, bsum, outdeg, rowptr, cursor, srcn, dstn, n, e);
    scatter_edges  <<<nbE, 256>>>(src, dst, srcn, cursor, edge, e);

    // ---- layer 1: h0 = relu(agg(hf)@W0*dn+b0); P = h0@Wo0 ----
    agg_h<<<nbAgH, 256>>>(hf, rowptr, edge, dstn, Ahi, Alo, n);
    conv_gemm<0><<<nbT, 256, SM_TOT>>>(Ahi, Alo,
                                       Bhi + 0 * DD * DD, Blo + 0 * DD * DD,
                                       Bhi + 3 * DD * DD, Blo + 3 * DD * DD,
                                       b0, h0, P, n);
    // ---- layer 2: h1; P += h1@Wo1 ----
    agg_h<<<nbAgH, 256>>>(h0, rowptr, edge, dstn, Ahi, Alo, n);
    conv_gemm<1><<<nbT, 256, SM_TOT>>>(Ahi, Alo,
                                       Bhi + 1 * DD * DD, Blo + 1 * DD * DD,
                                       Bhi + 4 * DD * DD, Blo + 4 * DD * DD,
                                       b1, h1, P, n);
    // ---- layer 3: h2 (not materialized); P += h2@Wo2 ----
    agg_h<<<nbAgH, 256>>>(h1, rowptr, edge, dstn, Ahi, Alo, n);
    conv_gemm<2><<<nbT, 256, SM_TOT>>>(Ahi, Alo,
                                       Bhi + 2 * DD * DD, Blo + 2 * DD * DD,
                                       Bhi + 5 * DD * DD, Blo + 5 * DD * DD,
                                       b2, nullptr, P, n);
    // ---- out = segsum(P) + bout ----
    pgather<<<nbAgW, 256>>>(P, rowptr, edge, bout, out, n);
}

// round 16
// speedup vs baseline: 1.0170x; 1.0170x over previous
#include <cuda_runtime.h>
#include <cuda_bf16.h>
#include <cuda_fp16.h>
#include <mma.h>
#include <cuda_pipeline.h>
#include <cstdint>

using namespace nvcuda;

// ---------------------------------------------------------------------------
// JKNet R16: R14 base (best: 352.2us) + PERSISTENT conv GEMM blocks:
// 296 blocks stage B+bias once, loop over tiles staging only A (32KB/tile).
// Removes redundant B staging (~50MB), shortens per-tile critical path,
// kills wave quantization. Final K=384 GEMM unchanged (B rotates anyway).
// ---------------------------------------------------------------------------

#define NN 50000
#define EE 800000
#define DD 128
#define NPAD (NN + 64)
#define PERSIST_BLOCKS 296   // 148 SMs x 2 blocks

// ---------------- scratch ---------------------------------------------------
__device__ __half g_hf[NN * DD];        // fp16 feats
__device__ __half g_h0[NN * DD];
__device__ __half g_h1[NN * DD];
__device__ __half g_h2[NN * DD];
__device__ __nv_bfloat16 g_Ahi[NPAD * DD];
__device__ __nv_bfloat16 g_Alo[NPAD * DD];
__device__ __nv_bfloat16 g_Fhi[3][NPAD * DD];
__device__ __nv_bfloat16 g_Flo[3][NPAD * DD];
__device__ float g_srcn[NN];
__device__ float g_dstn[NN];
__device__ int   g_outdeg[NN];
__device__ int   g_indeg [NN];
__device__ int   g_rowptr[NN + 1];
__device__ int   g_cursor[NN];
__device__ int2  g_edge[EE];            // (src, srcn bits)
__device__ int   g_bsum[256];
__device__ __nv_bfloat16 g_Bhi[6 * DD * DD];
__device__ __nv_bfloat16 g_Blo[6 * DD * DD];

// ---------------- CSR build -------------------------------------------------
__global__ void zero_ints(int* __restrict__ a, int* __restrict__ b, int n) {
    int i = blockIdx.x * blockDim.x + threadIdx.x;
    if (i < n) { a[i] = 0; b[i] = 0; }
}
__global__ void deg_hist(const int* __restrict__ src, const int* __restrict__ dst,
                         int* __restrict__ outdeg, int* __restrict__ indeg, int e) {
    int i = blockIdx.x * blockDim.x + threadIdx.x;
    if (i < e) { atomicAdd(&outdeg[src[i]], 1); atomicAdd(&indeg[dst[i]], 1); }
}
__global__ void scan_block_sums(const int* __restrict__ deg, int* __restrict__ bsum, int n) {
    __shared__ int s[256];
    int i = blockIdx.x * 256 + threadIdx.x;
    s[threadIdx.x] = (i < n) ? deg[i] : 0;
    __syncthreads();
    for (int off = 128; off > 0; off >>= 1) {
        if (threadIdx.x < off) s[threadIdx.x] += s[threadIdx.x + off];
        __syncthreads();
    }
    if (threadIdx.x == 0) bsum[blockIdx.x] = s[0];
}
__global__ void scan_bsums(int* __restrict__ bsum, int nb) {
    __shared__ int s[256];
    int t = threadIdx.x;
    int v = (t < nb) ? bsum[t] : 0;
    s[t] = v;
    __syncthreads();
    for (int off = 1; off < 256; off <<= 1) {
        int add = (t >= off) ? s[t - off] : 0;
        __syncthreads();
        s[t] += add;
        __syncthreads();
    }
    if (t < nb) bsum[t] = s[t] - v;
}
__global__ void scan_final(const int* __restrict__ deg, const int* __restrict__ bsum,
                           const int* __restrict__ outdeg,
                           int* __restrict__ rowptr, int* __restrict__ cursor,
                           float* __restrict__ sn, float* __restrict__ dn,
                           int n, int etot) {
    __shared__ int s[256];
    int t = threadIdx.x;
    int i = blockIdx.x * 256 + t;
    int v = (i < n) ? deg[i] : 0;
    s[t] = v;
    __syncthreads();
    for (int off = 1; off < 256; off <<= 1) {
        int add = (t >= off) ? s[t - off] : 0;
        __syncthreads();
        s[t] += add;
        __syncthreads();
    }
    int ex = bsum[blockIdx.x] + s[t] - v;
    if (i < n) {
        rowptr[i] = ex;
        cursor[i] = ex;
        sn[i] = rsqrtf((float)max(outdeg[i], 1));
        dn[i] = rsqrtf((float)max(v, 1));
    }
    if (i == 0) rowptr[n] = etot;
}
__global__ void scatter_edges(const int* __restrict__ src, const int* __restrict__ dst,
                              const float* __restrict__ srcn,
                              int* __restrict__ cursor, int2* __restrict__ edge, int e) {
    int i = blockIdx.x * blockDim.x + threadIdx.x;
    if (i < e) {
        int s = src[i];
        int p = atomicAdd(&cursor[dst[i]], 1);
        edge[p] = make_int2(s, __float_as_int(srcn[s]));
    }
}

// ---------------- input conversion: feats -> fp16, W -> bf16 hi/lo ----------
__global__ void conv_inputs(const float* __restrict__ feats,
                            const float* __restrict__ W0, const float* __restrict__ W1,
                            const float* __restrict__ W2, const float* __restrict__ Wout,
                            __half* __restrict__ hf,
                            __nv_bfloat16* __restrict__ hi, __nv_bfloat16* __restrict__ lo,
                            int nfeat4) {
    int idx = blockIdx.x * blockDim.x + threadIdx.x;
    if (idx < nfeat4) {
        float4 v = ((const float4*)feats)[idx];
        __half2 p0 = __floats2half2_rn(v.x, v.y);
        __half2 p1 = __floats2half2_rn(v.z, v.w);
        *(uint2*)(hf + (size_t)idx * 4) = make_uint2(*(uint32_t*)&p0, *(uint32_t*)&p1);
    }
    if (idx < 6 * DD * DD) {
        int m = idx / (DD * DD);
        int rem = idx % (DD * DD);
        const float* src = (m == 0) ? W0 : (m == 1) ? W1 : (m == 2) ? W2
                                         : (Wout + (m - 3) * DD * DD);
        float v = src[rem];
        __nv_bfloat16 h = __float2bfloat16(v);
        __nv_bfloat16 l = __float2bfloat16(v - __bfloat162float(h));
        hi[idx] = h;
        lo[idx] = l;
    }
}

// split 8 floats (cols sl*8..+7 of row r) into bf16 hi/lo images, 16B stores
__device__ __forceinline__ void split_store8(__nv_bfloat16* __restrict__ hi,
                                             __nv_bfloat16* __restrict__ lo,
                                             int r, int sl, const float* v) {
    uint4 ph, pl;
    uint32_t* phh = (uint32_t*)&ph;
    uint32_t* pll = (uint32_t*)&pl;
#pragma unroll
    for (int j = 0; j < 4; j++) {
        __nv_bfloat162 h2, l2;
        h2.x = __float2bfloat16(v[2 * j]);
        h2.y = __float2bfloat16(v[2 * j + 1]);
        l2.x = __float2bfloat16(v[2 * j]     - __bfloat162float(h2.x));
        l2.y = __float2bfloat16(v[2 * j + 1] - __bfloat162float(h2.y));
        phh[j] = *(uint32_t*)&h2;
        pll[j] = *(uint32_t*)&l2;
    }
    *(uint4*)(hi + (size_t)r * 128 + sl * 8) = ph;
    *(uint4*)(lo + (size_t)r * 128 + sl * 8) = pl;
}

// convert uint4 of 8 halves to 8 floats
__device__ __forceinline__ void cvt8(uint4 u, float* f) {
    __half2* h = (__half2*)&u;
#pragma unroll
    for (int j = 0; j < 4; j++) {
        float2 p = __half22float2(h[j]);
        f[2 * j] = p.x;
        f[2 * j + 1] = p.y;
    }
}

// ---------------- fp16 aggregation (half-warp per node) ---------------------
// MODE 0: A only. MODE 1: dual (A + F). MODE 2: F only.
template <int MODE>
__global__ void agg_h(const __half* __restrict__ X,
                      const int* __restrict__ rowptr,
                      const int2* __restrict__ edge,
                      const float* __restrict__ dstn,
                      __nv_bfloat16* __restrict__ Ahi, __nv_bfloat16* __restrict__ Alo,
                      __nv_bfloat16* __restrict__ Fhi, __nv_bfloat16* __restrict__ Flo,
                      int n) {
    int node = (blockIdx.x * blockDim.x + threadIdx.x) >> 4;   // half-warp per node
    int sl   = threadIdx.x & 15;
    if (node >= n) return;
    int beg = rowptr[node];
    int end = rowptr[node + 1];

    float aS[8], aP[8];
#pragma unroll
    for (int j = 0; j < 8; j++) { aS[j] = 0.f; aP[j] = 0.f; }

    int e = beg;
    for (; e + 7 < end; e += 8) {
        int2 ed[8];
#pragma unroll
        for (int t = 0; t < 8; t++) ed[t] = edge[e + t];
        uint4 u[8];
#pragma unroll
        for (int t = 0; t < 8; t++)
            u[t] = *(const uint4*)(X + (size_t)ed[t].x * 128 + sl * 8);
#pragma unroll
        for (int t = 0; t < 8; t++) {
            float f[8];
            cvt8(u[t], f);
            if (MODE != 2) {
                float nv = __int_as_float(ed[t].y);
#pragma unroll
                for (int j = 0; j < 8; j++) aS[j] += f[j] * nv;
            }
            if (MODE != 0) {
#pragma unroll
                for (int j = 0; j < 8; j++) aP[j] += f[j];
            }
        }
    }
    for (; e + 3 < end; e += 4) {
        int2 ed[4];
#pragma unroll
        for (int t = 0; t < 4; t++) ed[t] = edge[e + t];
        uint4 u[4];
#pragma unroll
        for (int t = 0; t < 4; t++)
            u[t] = *(const uint4*)(X + (size_t)ed[t].x * 128 + sl * 8);
#pragma unroll
        for (int t = 0; t < 4; t++) {
            float f[8];
            cvt8(u[t], f);
            if (MODE != 2) {
                float nv = __int_as_float(ed[t].y);
#pragma unroll
                for (int j = 0; j < 8; j++) aS[j] += f[j] * nv;
            }
            if (MODE != 0) {
#pragma unroll
                for (int j = 0; j < 8; j++) aP[j] += f[j];
            }
        }
    }
    for (; e < end; e++) {
        int2 e0 = edge[e];
        uint4 u0 = *(const uint4*)(X + (size_t)e0.x * 128 + sl * 8);
        float f0[8];
        cvt8(u0, f0);
        if (MODE != 2) {
            float n0 = __int_as_float(e0.y);
#pragma unroll
            for (int j = 0; j < 8; j++) aS[j] += f0[j] * n0;
        }
        if (MODE != 0) {
#pragma unroll
            for (int j = 0; j < 8; j++) aP[j] += f0[j];
        }
    }
    if (MODE != 2) {
        float dn = dstn[node];
#pragma unroll
        for (int j = 0; j < 8; j++) aS[j] *= dn;
        split_store8(Ahi, Alo, node, sl, aS);
    }
    if (MODE != 0) split_store8(Fhi, Flo, node, sl, aP);
}

// ---------------- smem layout ------------------------------------------------
#define ALD 136
#define BLD 136
#define SM_AHI 0
#define SM_ALO 17408
#define SM_BHI 34816
#define SM_BLO 69632
#define SM_BIAS 104448
#define SM_TOT 112640

// ---------------- persistent conv GEMM: H(fp16) = relu(A@W + bias) ----------
// B + bias staged ONCE per block; loop over tiles staging only A.
__global__ void __launch_bounds__(256, 2)
mma_conv(const __nv_bfloat16* __restrict__ Ah, const __nv_bfloat16* __restrict__ Al,
         const __nv_bfloat16* __restrict__ Bh, const __nv_bfloat16* __restrict__ Bl,
         const float* __restrict__ bias,
         __half* __restrict__ Hout, int n, int nTiles) {
    extern __shared__ unsigned char smem[];
    __nv_bfloat16* sAhi = (__nv_bfloat16*)(smem + SM_AHI);
    __nv_bfloat16* sAlo = (__nv_bfloat16*)(smem + SM_ALO);
    __nv_bfloat16* sBhi = (__nv_bfloat16*)(smem + SM_BHI);
    __nv_bfloat16* sBlo = (__nv_bfloat16*)(smem + SM_BLO);
    float*         sBias = (float*)(smem + SM_BIAS);
    float*         smemF = (float*)(smem + SM_AHI);   // 32KB fp32 result tile

    const int tid  = threadIdx.x;
    const int wid  = tid >> 5;
    const int rt = wid >> 1;
    const int ch = wid & 1;

    // ---- stage B + bias once ----
#pragma unroll
    for (int i = 0; i < 8; i++) {
        int idx = i * 256 + tid;
        int r   = idx >> 4;
        int c16 = idx & 15;
        __pipeline_memcpy_async(sBhi + r * BLD + c16 * 8, Bh + r * 128 + c16 * 8, 16);
        __pipeline_memcpy_async(sBlo + r * BLD + c16 * 8, Bl + r * 128 + c16 * 8, 16);
    }
    __pipeline_commit();
    for (int idx = tid; idx < 2048; idx += 256)
        sBias[idx] = bias[(idx >> 8) * 16 + (idx & 15)];

    for (int tile = blockIdx.x; tile < nTiles; tile += gridDim.x) {
        const int row0 = tile * 64;
        // ---- stage A for this tile ----
#pragma unroll
        for (int i = 0; i < 4; i++) {
            int idx = i * 256 + tid;
            int r   = idx >> 4;
            int c16 = idx & 15;
            size_t g = (size_t)(row0 + r) * 128 + c16 * 8;
            __pipeline_memcpy_async(sAhi + r * ALD + c16 * 8, Ah + g, 16);
            __pipeline_memcpy_async(sAlo + r * ALD + c16 * 8, Al + g, 16);
        }
        __pipeline_commit();
        __pipeline_wait_prior(0);
        __syncthreads();

        // ---- compute ----
        wmma::fragment<wmma::accumulator, 16, 16, 16, float> acc[4];
#pragma unroll
        for (int j = 0; j < 4; j++)
            wmma::load_matrix_sync(acc[j], sBias + (ch * 4 + j) * 256, 16,
                                   wmma::mem_row_major);
#pragma unroll
        for (int kk = 0; kk < 8; kk++) {
            wmma::fragment<wmma::matrix_a, 16, 16, 16, __nv_bfloat16, wmma::row_major> ah, al;
            wmma::load_matrix_sync(ah, sAhi + (rt * 16) * ALD + kk * 16, ALD);
            wmma::load_matrix_sync(al, sAlo + (rt * 16) * ALD + kk * 16, ALD);
#pragma unroll
            for (int j = 0; j < 4; j++) {
                int nt = ch * 4 + j;
                wmma::fragment<wmma::matrix_b, 16, 16, 16, __nv_bfloat16, wmma::row_major> bh, bl;
                wmma::load_matrix_sync(bh, sBhi + (kk * 16) * BLD + nt * 16, BLD);
                wmma::load_matrix_sync(bl, sBlo + (kk * 16) * BLD + nt * 16, BLD);
                wmma::mma_sync(acc[j], ah, bh, acc[j]);
                wmma::mma_sync(acc[j], ah, bl, acc[j]);
                wmma::mma_sync(acc[j], al, bh, acc[j]);
            }
        }

        // ---- epilogue: relu -> smemF -> fp16 global ----
        __syncthreads();   // A reads done; smemF may overwrite sA region
        if (row0 + rt * 16 + 16 <= n) {
#pragma unroll
            for (int j = 0; j < 4; j++) {
#pragma unroll
                for (int i = 0; i < acc[j].num_elements; i++)
                    acc[j].x[i] = fmaxf(acc[j].x[i], 0.f);
                wmma::store_matrix_sync(smemF + (rt * 16) * 128 + (ch * 4 + j) * 16,
                                        acc[j], 128, wmma::mem_row_major);
            }
        }
        __syncthreads();
#pragma unroll
        for (int i = 0; i < 8; i++) {
            int idx4 = i * 256 + tid;
            int r    = idx4 >> 5;
            int c4   = idx4 & 31;
            if (row0 + r < n) {
                float4 v = ((const float4*)smemF)[idx4];
                __half2 p0 = __floats2half2_rn(v.x, v.y);
                __half2 p1 = __floats2half2_rn(v.z, v.w);
                *(uint2*)(Hout + (size_t)(row0 + r) * 128 + c4 * 4) =
                    make_uint2(*(uint32_t*)&p0, *(uint32_t*)&p1);
            }
        }
        __syncthreads();   // smemF reads done before next tile's A staging
    }
}

// ---------------- final GEMM: C(fp32) = [F0 F1 F2] @ Wout + bout ------------
__global__ void __launch_bounds__(256, 2)
mma_final(const __nv_bfloat16* __restrict__ A0h, const __nv_bfloat16* __restrict__ A0l,
          const __nv_bfloat16* __restrict__ A1h, const __nv_bfloat16* __restrict__ A1l,
          const __nv_bfloat16* __restrict__ A2h, const __nv_bfloat16* __restrict__ A2l,
          const __nv_bfloat16* __restrict__ Bh0, const __nv_bfloat16* __restrict__ Bl0,
          const float* __restrict__ bias, float* __restrict__ Cout, int n) {
    extern __shared__ unsigned char smem[];
    __nv_bfloat16* sAhi = (__nv_bfloat16*)(smem + SM_AHI);
    __nv_bfloat16* sAlo = (__nv_bfloat16*)(smem + SM_ALO);
    __nv_bfloat16* sBhi = (__nv_bfloat16*)(smem + SM_BHI);
    __nv_bfloat16* sBlo = (__nv_bfloat16*)(smem + SM_BLO);
    float*         sBias = (float*)(smem + SM_BIAS);

    const int tid  = threadIdx.x;
    const int wid  = tid >> 5;
    const int row0 = blockIdx.x * 64;
    const int rt = wid >> 1;
    const int ch = wid & 1;

    const __nv_bfloat16* Ahs[3] = {A0h, A1h, A2h};
    const __nv_bfloat16* Als[3] = {A0l, A1l, A2l};
    wmma::fragment<wmma::accumulator, 16, 16, 16, float> acc[4];

#pragma unroll
    for (int seg = 0; seg < 3; seg++) {
        if (seg > 0) __syncthreads();
        {
            const __nv_bfloat16* Ah = Ahs[seg];
            const __nv_bfloat16* Al = Als[seg];
#pragma unroll
            for (int i = 0; i < 4; i++) {
                int idx = i * 256 + tid;
                int r   = idx >> 4;
                int c16 = idx & 15;
                size_t g = (size_t)(row0 + r) * 128 + c16 * 8;
                __pipeline_memcpy_async(sAhi + r * ALD + c16 * 8, Ah + g, 16);
                __pipeline_memcpy_async(sAlo + r * ALD + c16 * 8, Al + g, 16);
            }
        }
        {
            const __nv_bfloat16* Bh = Bh0 + seg * DD * DD;
            const __nv_bfloat16* Bl = Bl0 + seg * DD * DD;
#pragma unroll
            for (int i = 0; i < 8; i++) {
                int idx = i * 256 + tid;
                int r   = idx >> 4;
                int c16 = idx & 15;
                __pipeline_memcpy_async(sBhi + r * BLD + c16 * 8, Bh + r * 128 + c16 * 8, 16);
                __pipeline_memcpy_async(sBlo + r * BLD + c16 * 8, Bl + r * 128 + c16 * 8, 16);
            }
        }
        __pipeline_commit();
        if (seg == 0) {
            for (int idx = tid; idx < 2048; idx += 256)
                sBias[idx] = bias[(idx >> 8) * 16 + (idx & 15)];
        }
        __pipeline_wait_prior(0);
        __syncthreads();

        if (seg == 0) {
#pragma unroll
            for (int j = 0; j < 4; j++)
                wmma::load_matrix_sync(acc[j], sBias + (ch * 4 + j) * 256, 16,
                                       wmma::mem_row_major);
        }
#pragma unroll
        for (int kk = 0; kk < 8; kk++) {
            wmma::fragment<wmma::matrix_a, 16, 16, 16, __nv_bfloat16, wmma::row_major> ah, al;
            wmma::load_matrix_sync(ah, sAhi + (rt * 16) * ALD + kk * 16, ALD);
            wmma::load_matrix_sync(al, sAlo + (rt * 16) * ALD + kk * 16, ALD);
#pragma unroll
            for (int j = 0; j < 4; j++) {
                int nt = ch * 4 + j;
                wmma::fragment<wmma::matrix_b, 16, 16, 16, __nv_bfloat16, wmma::row_major> bh, bl;
                wmma::load_matrix_sync(bh, sBhi + (kk * 16) * BLD + nt * 16, BLD);
                wmma::load_matrix_sync(bl, sBlo + (kk * 16) * BLD + nt * 16, BLD);
                wmma::mma_sync(acc[j], ah, bh, acc[j]);
                wmma::mma_sync(acc[j], ah, bl, acc[j]);
                wmma::mma_sync(acc[j], al, bh, acc[j]);
            }
        }
    }

    if (row0 + rt * 16 + 16 <= n) {
#pragma unroll
        for (int j = 0; j < 4; j++)
            wmma::store_matrix_sync(Cout + (size_t)(row0 + rt * 16) * 128 + (ch * 4 + j) * 16,
                                    acc[j], 128, wmma::mem_row_major);
    }
}

// ---------------------------------------------------------------------------
extern "C" void kernel_launch(void* const* d_in, const int* in_sizes, int n_in,
                              void* d_out, int out_size) {
    const float* feats = (const float*)d_in[0];
    const int*   src   = (const int*)  d_in[1];
    const int*   dst   = (const int*)  d_in[2];
    const float* W0    = (const float*)d_in[3];
    const float* b0    = (const float*)d_in[4];
    const float* W1    = (const float*)d_in[5];
    const float* b1    = (const float*)d_in[6];
    const float* W2    = (const float*)d_in[7];
    const float* b2    = (const float*)d_in[8];
    const float* Wout  = (const float*)d_in[9];
    const float* bout  = (const float*)d_in[10];
    float*       out   = (float*)d_out;

    const int n = in_sizes[0] / DD;
    const int e = in_sizes[1];

    __half *hf, *h0, *h1, *h2;
    float *srcn, *dstn;
    int *outdeg, *indeg, *rowptr, *cursor, *bsum;
    int2 *edge;
    __nv_bfloat16 *Ahi, *Alo, *Fhi, *Flo, *Bhi, *Blo;
    cudaGetSymbolAddress((void**)&hf,     g_hf);
    cudaGetSymbolAddress((void**)&h0,     g_h0);
    cudaGetSymbolAddress((void**)&h1,     g_h1);
    cudaGetSymbolAddress((void**)&h2,     g_h2);
    cudaGetSymbolAddress((void**)&Ahi,    g_Ahi);
    cudaGetSymbolAddress((void**)&Alo,    g_Alo);
    cudaGetSymbolAddress((void**)&Fhi,    g_Fhi);
    cudaGetSymbolAddress((void**)&Flo,    g_Flo);
    cudaGetSymbolAddress((void**)&srcn,   g_srcn);
    cudaGetSymbolAddress((void**)&dstn,   g_dstn);
    cudaGetSymbolAddress((void**)&outdeg, g_outdeg);
    cudaGetSymbolAddress((void**)&indeg,  g_indeg);
    cudaGetSymbolAddress((void**)&rowptr, g_rowptr);
    cudaGetSymbolAddress((void**)&cursor, g_cursor);
    cudaGetSymbolAddress((void**)&edge,   g_edge);
    cudaGetSymbolAddress((void**)&bsum,   g_bsum);
    cudaGetSymbolAddress((void**)&Bhi,    g_Bhi);
    cudaGetSymbolAddress((void**)&Blo,    g_Blo);

    const int nbN   = (n + 255) / 256;
    const int nbE   = (e + 255) / 256;
    const int nbAgH = (n + 15) / 16;
    const int nbT   = (n + 63) / 64;     // 782 tiles
    const int nfeat4 = n * DD / 4;
    const int nbCv  = (nfeat4 + 255) / 256;

    cudaFuncSetAttribute(mma_conv,  cudaFuncAttributeMaxDynamicSharedMemorySize, SM_TOT);
    cudaFuncSetAttribute(mma_final, cudaFuncAttributeMaxDynamicSharedMemorySize, SM_TOT);

    // ---- CSR build + norms + input conversion ----
    zero_ints      <<<nbN, 256>>>(outdeg, indeg, n);
    conv_inputs    <<<nbCv, 256>>>(feats, W0, W1, W2, Wout, hf, Bhi, Blo, nfeat4);
    deg_hist       <<<nbE, 256>>>(src, dst, outdeg, indeg, e);
    scan_block_sums<<<nbN, 256>>>(indeg, bsum, n);
    scan_bsums     <<<1,   256>>>(bsum, nbN);
    scan_final     <<<nbN, 256>>>(indeg, bsum, outdeg, rowptr, cursor, srcn, dstn, n, e);
    scatter_edges  <<<nbE, 256>>>(src, dst, srcn, cursor, edge, e);

    // ---- layer 1 ----
    agg_h<0><<<nbAgH, 256>>>(hf, rowptr, edge, dstn, Ahi, Alo, nullptr, nullptr, n);
    mma_conv<<<PERSIST_BLOCKS, 256, SM_TOT>>>(Ahi, Alo,
                                              Bhi + 0 * DD * DD, Blo + 0 * DD * DD,
                                              b0, h0, n, nbT);
    // ---- layer 2 (+ F0) ----
    agg_h<1><<<nbAgH, 256>>>(h0, rowptr, edge, dstn,
                             Ahi, Alo, Fhi + 0 * NPAD * DD, Flo + 0 * NPAD * DD, n);
    mma_conv<<<PERSIST_BLOCKS, 256, SM_TOT>>>(Ahi, Alo,
                                              Bhi + 1 * DD * DD, Blo + 1 * DD * DD,
                                              b1, h1, n, nbT);
    // ---- layer 3 (+ F1) ----
    agg_h<1><<<nbAgH, 256>>>(h1, rowptr, edge, dstn,
                             Ahi, Alo, Fhi + 1 * NPAD * DD, Flo + 1 * NPAD * DD, n);
    mma_conv<<<PERSIST_BLOCKS, 256, SM_TOT>>>(Ahi, Alo,
                                              Bhi + 2 * DD * DD, Blo + 2 * DD * DD,
                                              b2, h2, n, nbT);
    // ---- F2 = plain agg(h2) ----
    agg_h<2><<<nbAgH, 256>>>(h2, rowptr, edge, dstn,
                             nullptr, nullptr,
                             Fhi + 2 * NPAD * DD, Flo + 2 * NPAD * DD, n);
    // ---- out = [F0 F1 F2] @ Wout + bout ----
    mma_final<<<nbT, 256, SM_TOT>>>(Fhi + 0 * NPAD * DD, Flo + 0 * NPAD * DD,
                                    Fhi + 1 * NPAD * DD, Flo + 1 * NPAD * DD,
                                    Fhi + 2 * NPAD * DD, Flo + 2 * NPAD * DD,
                                    Bhi + 3 * DD * DD, Blo + 3 * DD * DD,
                                    bout, out, n);
}